// round 7
// baseline (speedup 1.0000x reference)
#include <cuda_runtime.h>

// Problem shape (fixed by the dataset)
#define BB 4
#define NN 8192
#define MM 2048
#define FF 256
#define KK 16
#define CH (3 + FF)   // 259 output channels

// Scratch (static __device__ — no allocations allowed)
__device__ __align__(16) float4 g_pts4[BB * NN];   // packed xyz + |p|^2
__device__ int    g_idx [BB * MM * KK];            // neighbor indices
__device__ float  g_w   [BB * MM * KK];            // softmax weights
__device__ __align__(16) float g_T[(size_t)BB * NN * FF];  // (B,N,F), 33.5MB

// ---------------------------------------------------------------------------
// K0: pack point cloud (B,3,N) -> float4 (x,y,z,|p|^2)
// ---------------------------------------------------------------------------
__global__ void k_pack(const float* __restrict__ pc) {
    int i = blockIdx.x * blockDim.x + threadIdx.x;
    if (i >= BB * NN) return;
    int b = i / NN, n = i - b * NN;
    const float* base = pc + (size_t)b * 3 * NN;
    float x = base[n], y = base[NN + n], z = base[2 * NN + n];
    g_pts4[i] = make_float4(x, y, z, fmaf(x, x, fmaf(y, y, z * z)));
}

// ---------------------------------------------------------------------------
// K1: warp-per-query KNN (k=16) + softmax weights + projected points.
// (Round-5 structure: 8192 warps, ~55/SM — occupancy is load-bearing here,
// the insert path is a ~100-cycle dependent shuffle chain.)
// Lanes 0..15 hold a distributed ascending-sorted (d', idx) list where
// d' = |p|^2 - 2 q.p (= true d^2 - |q|^2; same order; softmax uses only
// differences so the offset cancels exactly).
// Fused-pair ballots: one warp vote per 64 points in the common path.
// ---------------------------------------------------------------------------
__global__ void k_knn(const float* __restrict__ qc,
                      const float* __restrict__ temp,
                      float* __restrict__ out) {
    const unsigned FULL = 0xFFFFFFFFu;
    int gw   = (blockIdx.x * blockDim.x + threadIdx.x) >> 5;  // query id
    int lane = threadIdx.x & 31;
    int b = gw / MM, m = gw - b * MM;

    const float* qb = qc + (size_t)b * 3 * MM;
    float n2x = -2.0f * qb[m];
    float n2y = -2.0f * qb[MM + m];
    float n2z = -2.0f * qb[2 * MM + m];

    const float4* pts = g_pts4 + (size_t)b * NN;

    float ld  = __int_as_float(0x7f800000);  // +inf
    int   li  = 0;
    float tau = ld;                          // current worst of the 16 (list[15])

#define PROCESS(dv, boff)                                                   \
    {                                                                        \
        unsigned ball = __ballot_sync(FULL, (dv) < tau);                     \
        while (ball) {                                                       \
            int src = __ffs(ball) - 1;                                       \
            ball &= ball - 1;                                                \
            float dc = __shfl_sync(FULL, (dv), src);                         \
            if (dc < tau) {                                                  \
                int ic = (boff) + src;                                       \
                unsigned less = __ballot_sync(FULL, (lane < KK) && (ld < dc));\
                int pos = __popc(less);                                      \
                float pld = __shfl_up_sync(FULL, ld, 1);                     \
                int   pli = __shfl_up_sync(FULL, li, 1);                     \
                if (lane < KK) {                                             \
                    if (lane > pos)       { ld = pld; li = pli; }            \
                    else if (lane == pos) { ld = dc;  li = ic;  }            \
                }                                                            \
                tau = __shfl_sync(FULL, ld, KK - 1);                         \
            }                                                                \
        }                                                                    \
    }

    for (int base = 0; base < NN; base += 128) {
        float4 p0 = pts[base +       lane];
        float4 p1 = pts[base +  32 + lane];
        float4 p2 = pts[base +  64 + lane];
        float4 p3 = pts[base +  96 + lane];
        float d0 = fmaf(p0.x, n2x, fmaf(p0.y, n2y, fmaf(p0.z, n2z, p0.w)));
        float d1 = fmaf(p1.x, n2x, fmaf(p1.y, n2y, fmaf(p1.z, n2z, p1.w)));
        float d2 = fmaf(p2.x, n2x, fmaf(p2.y, n2y, fmaf(p2.z, n2z, p2.w)));
        float d3 = fmaf(p3.x, n2x, fmaf(p3.y, n2y, fmaf(p3.z, n2z, p3.w)));
        // fused-pair vote: common (no-candidate) path pays 1 ballot / 64 pts;
        // PROCESS re-ballots its own sub-group, so triggering is safe.
        unsigned any01 = __ballot_sync(FULL, fminf(d0, d1) < tau);
        if (any01) { PROCESS(d0, base);      PROCESS(d1, base + 32); }
        unsigned any23 = __ballot_sync(FULL, fminf(d2, d3) < tau);
        if (any23) { PROCESS(d2, base + 64); PROCESS(d3, base + 96); }
    }
#undef PROCESS

    // softmax(-(d - dmin)/sigma) over the 16 neighbors (offset cancels)
    float tv    = *temp;
    float sigma = fmaxf(tv * tv, 1e-4f);
    float dmin  = __shfl_sync(FULL, ld, 0);  // ascending list -> lane0 is min
    float e = (lane < KK) ? __expf((dmin - ld) / sigma) : 0.0f;
    float s = e;
    #pragma unroll
    for (int off = 16; off >= 1; off >>= 1) s += __shfl_xor_sync(FULL, s, off);
    float w = e / s;

    if (lane < KK) {
        g_idx[gw * KK + lane] = li;
        g_w  [gw * KK + lane] = w;
    }

    // projected points = sum_j w_j * p_j
    float4 gp = make_float4(0.f, 0.f, 0.f, 0.f);
    if (lane < KK) gp = pts[li];
    float sx = w * gp.x, sy = w * gp.y, sz = w * gp.z;
    #pragma unroll
    for (int off = 16; off >= 1; off >>= 1) {
        sx += __shfl_xor_sync(FULL, sx, off);
        sy += __shfl_xor_sync(FULL, sy, off);
        sz += __shfl_xor_sync(FULL, sz, off);
    }
    if (lane == 0) {
        float* ob = out + (size_t)b * CH * MM;
        ob[m]          = sx;
        ob[MM + m]     = sy;
        ob[2 * MM + m] = sz;
    }
}

// ---------------------------------------------------------------------------
// K2: transpose features (B,F,N) -> (B,N,F). float4 loads along N, float4
// stores along F through a padded conflict-free 32x32 tile.
// ---------------------------------------------------------------------------
__global__ void k_transpose(const float* __restrict__ feat) {
    __shared__ float t[32][33];
    int b  = blockIdx.z;
    int n0 = blockIdx.x * 32, f0 = blockIdx.y * 32;
    int tid = threadIdx.x;                 // 256 threads
    const float* fb = feat + (size_t)b * FF * NN;

    int f = tid >> 3, nc = tid & 7;        // f row, 4-wide n chunk
    float4 v = *(const float4*)(fb + (size_t)(f0 + f) * NN + n0 + 4 * nc);
    t[4 * nc + 0][f] = v.x;
    t[4 * nc + 1][f] = v.y;
    t[4 * nc + 2][f] = v.z;
    t[4 * nc + 3][f] = v.w;
    __syncthreads();

    int n = tid >> 3, fc = tid & 7;        // n row, 4-wide f chunk
    float4 w = make_float4(t[n][4 * fc], t[n][4 * fc + 1],
                           t[n][4 * fc + 2], t[n][4 * fc + 3]);
    *(float4*)(g_T + (size_t)b * NN * FF + (size_t)(n0 + n) * FF + f0 + 4 * fc) = w;
}

// ---------------------------------------------------------------------------
// K3 (fused gather + output transpose): one block per (32-feature, 32-query,
// batch) tile; f-tile is the FAST grid dimension so blocks consuming
// different segments of the same gathered rows run concurrently.
// ---------------------------------------------------------------------------
__global__ void k_gather_out(float* __restrict__ out) {
    __shared__ int   sidx[32][KK];
    __shared__ float sw  [32][KK];
    __shared__ float tile[32][33];   // [f_in_tile][query]

    int tid = threadIdx.x;           // 256 threads
    int f0 = blockIdx.x * 32;
    int m0 = blockIdx.y * 32;
    int b  = blockIdx.z;

    {
        int base = (b * MM + m0) * KK;
        #pragma unroll
        for (int t2 = tid; t2 < 32 * KK; t2 += 256) {
            ((int*)sidx)[t2] = g_idx[base + t2];
            ((float*)sw)[t2] = g_w  [base + t2];
        }
    }
    __syncthreads();

    int qi = tid >> 3;               // query in tile
    int xq = tid & 7;                // float4 chunk of the 32 features
    const float4* Tb4 = (const float4*)(g_T + (size_t)b * NN * FF) + (f0 >> 2) + xq;
    float4 acc = make_float4(0.f, 0.f, 0.f, 0.f);
    #pragma unroll
    for (int j = 0; j < KK; j++) {
        float  wj = sw[qi][j];
        float4 v  = Tb4[(size_t)sidx[qi][j] * (FF / 4)];
        acc.x = fmaf(wj, v.x, acc.x);
        acc.y = fmaf(wj, v.y, acc.y);
        acc.z = fmaf(wj, v.z, acc.z);
        acc.w = fmaf(wj, v.w, acc.w);
    }
    tile[4 * xq + 0][qi] = acc.x;    // bank (4xq+j+qi) mod 32: conflict-free
    tile[4 * xq + 1][qi] = acc.y;
    tile[4 * xq + 2][qi] = acc.z;
    tile[4 * xq + 3][qi] = acc.w;
    __syncthreads();

    int x  = tid & 31;
    int y0 = tid >> 5;
    float* dst = out + (size_t)b * CH * MM;
    #pragma unroll
    for (int r = 0; r < 4; r++) {
        int f = y0 + r * 8;
        dst[(size_t)(3 + f0 + f) * MM + m0 + x] = tile[f][x];
    }
}

// ---------------------------------------------------------------------------
// Side-stream infrastructure for overlapping the (DRAM-bound) transpose with
// the (L1/issue-bound) KNN. Created once on the first (uncaptured,
// correctness) call; no device memory is allocated, and every call performs
// the identical, deterministic set of launches/records/waits.
// ---------------------------------------------------------------------------
static cudaStream_t g_s2;
static cudaEvent_t  g_e_fork, g_e_join;
static bool         g_init_done = false;

extern "C" void kernel_launch(void* const* d_in, const int* in_sizes, int n_in,
                              void* d_out, int out_size) {
    (void)in_sizes; (void)n_in; (void)out_size;
    const float* pc   = (const float*)d_in[0];  // (B,3,N)
    const float* qc   = (const float*)d_in[1];  // (B,3,M)
    const float* feat = (const float*)d_in[2];  // (B,F,N)
    const float* temp = (const float*)d_in[3];  // scalar
    float* out = (float*)d_out;                 // (B,259,M)

    if (!g_init_done) {
        cudaStreamCreateWithFlags(&g_s2, cudaStreamNonBlocking);
        cudaEventCreateWithFlags(&g_e_fork, cudaEventDisableTiming);
        cudaEventCreateWithFlags(&g_e_join, cudaEventDisableTiming);
        g_init_done = true;
    }

    // fork: side stream runs the feature transpose concurrently with KNN
    cudaEventRecord(g_e_fork, 0);
    cudaStreamWaitEvent(g_s2, g_e_fork, 0);
    k_transpose<<<dim3(NN / 32, FF / 32, BB), 256, 0, g_s2>>>(feat);
    cudaEventRecord(g_e_join, g_s2);

    // main stream: pack -> knn
    k_pack<<<(BB * NN + 255) / 256, 256>>>(pc);
    k_knn<<<(BB * MM) / 8, 256>>>(qc, temp, out);

    // join: gather needs both knn results and g_T
    cudaStreamWaitEvent(0, g_e_join, 0);
    k_gather_out<<<dim3(FF / 32, MM / 32, BB), 256>>>(out);
}

// round 10
// speedup vs baseline: 1.6727x; 1.6727x over previous
#include <cuda_runtime.h>

// Problem shape (fixed by the dataset)
#define BB 4
#define NN 8192
#define MM 2048
#define FF 256
#define KK 16
#define CH (3 + FF)   // 259 output channels

// Scratch (static __device__ — no allocations allowed)
__device__ __align__(16) float4 g_pts4[BB * NN];   // packed xyz + |p|^2
__device__ int    g_idx [BB * MM * KK];            // neighbor indices
__device__ float  g_w   [BB * MM * KK];            // softmax weights
__device__ __align__(16) float g_T[(size_t)BB * NN * FF];  // (B,N,F), 33.5MB

// ---------------------------------------------------------------------------
// K0: pack point cloud (B,3,N) -> float4 (x,y,z,|p|^2)
// ---------------------------------------------------------------------------
__global__ void k_pack(const float* __restrict__ pc) {
    int i = blockIdx.x * blockDim.x + threadIdx.x;
    if (i >= BB * NN) return;
    int b = i / NN, n = i - b * NN;
    const float* base = pc + (size_t)b * 3 * NN;
    float x = base[n], y = base[NN + n], z = base[2 * NN + n];
    g_pts4[i] = make_float4(x, y, z, fmaf(x, x, fmaf(y, y, z * z)));
}

// ---------------------------------------------------------------------------
// K1: warp-per-query KNN (k=16) + softmax weights + projected points.
// 8192 warps (~55/SM): occupancy is load-bearing — the insert path is a
// ~110-cycle dependent shuffle chain, hidden only by other warps.
// Lanes 0..15 hold a distributed ascending-sorted (d', idx) list with
// d' = |p|^2 - 2 q.p (= true d^2 - |q|^2: same order; softmax uses only
// differences so the constant offset cancels exactly).
// Bootstrap: a 32-lane bitonic sort of the first 32 points replaces the
// ~32 serialized startup inserts (tau=inf) with ~15 parallel stages.
// ---------------------------------------------------------------------------
__global__ void k_knn(const float* __restrict__ qc,
                      const float* __restrict__ temp,
                      float* __restrict__ out) {
    const unsigned FULL = 0xFFFFFFFFu;
    int gw   = (blockIdx.x * blockDim.x + threadIdx.x) >> 5;  // query id
    int lane = threadIdx.x & 31;
    int b = gw / MM, m = gw - b * MM;

    const float* qb = qc + (size_t)b * 3 * MM;
    float n2x = -2.0f * qb[m];
    float n2y = -2.0f * qb[MM + m];
    float n2z = -2.0f * qb[2 * MM + m];

    const float4* pts = g_pts4 + (size_t)b * NN;

    float ld;      // this lane's list entry (ascending over lanes 0..15)
    int   li;
    float tau;     // current worst of the 16 (= list[15])

#define PROCESS(dv, boff)                                                   \
    {                                                                        \
        unsigned ball = __ballot_sync(FULL, (dv) < tau);                     \
        while (ball) {                                                       \
            int src = __ffs(ball) - 1;                                       \
            ball &= ball - 1;                                                \
            float dc = __shfl_sync(FULL, (dv), src);                         \
            if (dc < tau) {                                                  \
                int ic = (boff) + src;                                       \
                unsigned less = __ballot_sync(FULL, (lane < KK) && (ld < dc));\
                int pos = __popc(less);                                      \
                float pld = __shfl_up_sync(FULL, ld, 1);                     \
                int   pli = __shfl_up_sync(FULL, li, 1);                     \
                if (lane < KK) {                                             \
                    if (lane > pos)       { ld = pld; li = pli; }            \
                    else if (lane == pos) { ld = dc;  li = ic;  }            \
                }                                                            \
                tau = __shfl_sync(FULL, ld, KK - 1);                         \
            }                                                                \
        }                                                                    \
    }

    // ---- bootstrap block: points 0..127 ----
    {
        float4 p0 = pts[lane];
        float4 p1 = pts[32 + lane];
        float4 p2 = pts[64 + lane];
        float4 p3 = pts[96 + lane];
        float d0 = fmaf(p0.x, n2x, fmaf(p0.y, n2y, fmaf(p0.z, n2z, p0.w)));
        float d1 = fmaf(p1.x, n2x, fmaf(p1.y, n2y, fmaf(p1.z, n2z, p1.w)));
        float d2 = fmaf(p2.x, n2x, fmaf(p2.y, n2y, fmaf(p2.z, n2z, p2.w)));
        float d3 = fmaf(p3.x, n2x, fmaf(p3.y, n2y, fmaf(p3.z, n2z, p3.w)));

        // bitonic sort of (d0, lane) ascending across the 32 lanes
        float sd = d0; int si = lane;
        #pragma unroll
        for (int k = 2; k <= 32; k <<= 1) {
            #pragma unroll
            for (int j = k >> 1; j > 0; j >>= 1) {
                float od = __shfl_xor_sync(FULL, sd, j);
                int   oi = __shfl_xor_sync(FULL, si, j);
                bool keep_min = (((lane & k) == 0) == ((lane & j) == 0));
                bool take_other = keep_min ? (od < sd) : (od > sd);
                if (take_other) { sd = od; si = oi; }
            }
        }
        ld  = sd;                         // lanes 0..15 = smallest 16, sorted
        li  = si;
        tau = __shfl_sync(FULL, ld, KK - 1);

        PROCESS(d1, 32);
        PROCESS(d2, 64);
        PROCESS(d3, 96);
    }

    // ---- main scan: fused-pair votes (1 ballot / 64 pts in common path) ----
    for (int base = 128; base < NN; base += 128) {
        float4 p0 = pts[base +       lane];
        float4 p1 = pts[base +  32 + lane];
        float4 p2 = pts[base +  64 + lane];
        float4 p3 = pts[base +  96 + lane];
        float d0 = fmaf(p0.x, n2x, fmaf(p0.y, n2y, fmaf(p0.z, n2z, p0.w)));
        float d1 = fmaf(p1.x, n2x, fmaf(p1.y, n2y, fmaf(p1.z, n2z, p1.w)));
        float d2 = fmaf(p2.x, n2x, fmaf(p2.y, n2y, fmaf(p2.z, n2z, p2.w)));
        float d3 = fmaf(p3.x, n2x, fmaf(p3.y, n2y, fmaf(p3.z, n2z, p3.w)));
        unsigned any01 = __ballot_sync(FULL, fminf(d0, d1) < tau);
        if (any01) { PROCESS(d0, base);      PROCESS(d1, base + 32); }
        unsigned any23 = __ballot_sync(FULL, fminf(d2, d3) < tau);
        if (any23) { PROCESS(d2, base + 64); PROCESS(d3, base + 96); }
    }
#undef PROCESS

    // softmax(-(d - dmin)/sigma) over the 16 neighbors (offset cancels)
    float tv    = *temp;
    float sigma = fmaxf(tv * tv, 1e-4f);
    float dmin  = __shfl_sync(FULL, ld, 0);  // ascending list -> lane0 is min
    float e = (lane < KK) ? __expf((dmin - ld) / sigma) : 0.0f;
    float s = e;
    #pragma unroll
    for (int off = 16; off >= 1; off >>= 1) s += __shfl_xor_sync(FULL, s, off);
    float w = e / s;

    if (lane < KK) {
        g_idx[gw * KK + lane] = li;
        g_w  [gw * KK + lane] = w;
    }

    // projected points = sum_j w_j * p_j
    float4 gp = make_float4(0.f, 0.f, 0.f, 0.f);
    if (lane < KK) gp = pts[li];
    float sx = w * gp.x, sy = w * gp.y, sz = w * gp.z;
    #pragma unroll
    for (int off = 16; off >= 1; off >>= 1) {
        sx += __shfl_xor_sync(FULL, sx, off);
        sy += __shfl_xor_sync(FULL, sy, off);
        sz += __shfl_xor_sync(FULL, sz, off);
    }
    if (lane == 0) {
        float* ob = out + (size_t)b * CH * MM;
        ob[m]          = sx;
        ob[MM + m]     = sy;
        ob[2 * MM + m] = sz;
    }
}

// ---------------------------------------------------------------------------
// K2: transpose features (B,F,N) -> (B,N,F). float4 loads along N, float4
// stores along F through a padded conflict-free 32x32 tile.
// ---------------------------------------------------------------------------
__global__ void k_transpose(const float* __restrict__ feat) {
    __shared__ float t[32][33];
    int b  = blockIdx.z;
    int n0 = blockIdx.x * 32, f0 = blockIdx.y * 32;
    int tid = threadIdx.x;                 // 256 threads
    const float* fb = feat + (size_t)b * FF * NN;

    int f = tid >> 3, nc = tid & 7;        // f row, 4-wide n chunk
    float4 v = *(const float4*)(fb + (size_t)(f0 + f) * NN + n0 + 4 * nc);
    t[4 * nc + 0][f] = v.x;
    t[4 * nc + 1][f] = v.y;
    t[4 * nc + 2][f] = v.z;
    t[4 * nc + 3][f] = v.w;
    __syncthreads();

    int n = tid >> 3, fc = tid & 7;        // n row, 4-wide f chunk
    float4 w = make_float4(t[n][4 * fc], t[n][4 * fc + 1],
                           t[n][4 * fc + 2], t[n][4 * fc + 3]);
    *(float4*)(g_T + (size_t)b * NN * FF + (size_t)(n0 + n) * FF + f0 + 4 * fc) = w;
}

// ---------------------------------------------------------------------------
// K3 (fused gather + output transpose): one block per (32-feature, 32-query,
// batch) tile; f-tile is the FAST grid dimension so blocks consuming
// different segments of the same gathered rows run concurrently.
// ---------------------------------------------------------------------------
__global__ void k_gather_out(float* __restrict__ out) {
    __shared__ int   sidx[32][KK];
    __shared__ float sw  [32][KK];
    __shared__ float tile[32][33];   // [f_in_tile][query]

    int tid = threadIdx.x;           // 256 threads
    int f0 = blockIdx.x * 32;
    int m0 = blockIdx.y * 32;
    int b  = blockIdx.z;

    {
        int base = (b * MM + m0) * KK;
        #pragma unroll
        for (int t2 = tid; t2 < 32 * KK; t2 += 256) {
            ((int*)sidx)[t2] = g_idx[base + t2];
            ((float*)sw)[t2] = g_w  [base + t2];
        }
    }
    __syncthreads();

    int qi = tid >> 3;               // query in tile
    int xq = tid & 7;                // float4 chunk of the 32 features
    const float4* Tb4 = (const float4*)(g_T + (size_t)b * NN * FF) + (f0 >> 2) + xq;
    float4 acc = make_float4(0.f, 0.f, 0.f, 0.f);
    #pragma unroll
    for (int j = 0; j < KK; j++) {
        float  wj = sw[qi][j];
        float4 v  = Tb4[(size_t)sidx[qi][j] * (FF / 4)];
        acc.x = fmaf(wj, v.x, acc.x);
        acc.y = fmaf(wj, v.y, acc.y);
        acc.z = fmaf(wj, v.z, acc.z);
        acc.w = fmaf(wj, v.w, acc.w);
    }
    tile[4 * xq + 0][qi] = acc.x;    // bank (4xq+j+qi) mod 32: conflict-free
    tile[4 * xq + 1][qi] = acc.y;
    tile[4 * xq + 2][qi] = acc.z;
    tile[4 * xq + 3][qi] = acc.w;
    __syncthreads();

    int x  = tid & 31;
    int y0 = tid >> 5;
    float* dst = out + (size_t)b * CH * MM;
    #pragma unroll
    for (int r = 0; r < 4; r++) {
        int f = y0 + r * 8;
        dst[(size_t)(3 + f0 + f) * MM + m0 + x] = tile[f][x];
    }
}

// ---------------------------------------------------------------------------
extern "C" void kernel_launch(void* const* d_in, const int* in_sizes, int n_in,
                              void* d_out, int out_size) {
    (void)in_sizes; (void)n_in; (void)out_size;
    const float* pc   = (const float*)d_in[0];  // (B,3,N)
    const float* qc   = (const float*)d_in[1];  // (B,3,M)
    const float* feat = (const float*)d_in[2];  // (B,F,N)
    const float* temp = (const float*)d_in[3];  // scalar
    float* out = (float*)d_out;                 // (B,259,M)

    k_pack<<<(BB * NN + 255) / 256, 256>>>(pc);
    k_knn<<<(BB * MM) / 8, 256>>>(qc, temp, out);
    k_transpose<<<dim3(NN / 32, FF / 32, BB), 256>>>(feat);
    k_gather_out<<<dim3(FF / 32, MM / 32, BB), 256>>>(out);
}